// round 11
// baseline (speedup 1.0000x reference)
#include <cuda_runtime.h>
#include <cuda_fp16.h>
#include <math.h>

#define PI_F 3.14159f

// Scratch: __device__ global (no allocation allowed)
__device__ float g_par[4 * 256 * 4];  // per (b,c): m0=scale*cos, m1=scale*sin, tx, ty

// ---------------- Fused MLP (single launch) ---------------------------------
// grid = 64 (b*16 + cg), block = 256. Each block redundantly computes the
// full stage-1 vector p[256] for batch b (coalesced W1 reads), then the
// coalesced stage-2 heads for its 16 channels.
__global__ void mlp_fused_kernel(const float* __restrict__ pc,
                                 const float* __restrict__ W1, const float* __restrict__ b1,
                                 const float* __restrict__ Ws, const float* __restrict__ bs,
                                 const float* __restrict__ Wr, const float* __restrict__ br,
                                 const float* __restrict__ Wt, const float* __restrict__ bt) {
    int blk = blockIdx.x;
    int b = blk >> 4;
    int cg = blk & 15;
    int tid = threadIdx.x;
    __shared__ float s[256];
    __shared__ float p[256];
    __shared__ float4 part[256];

    s[tid] = pc[b * 256 + tid];
    __syncthreads();

    // stage 1: thread tid computes p[tid] = relu(sum_k s[k]*W1[k,tid] + b1[tid])
    {
        float acc = b1[tid];
#pragma unroll 8
        for (int k = 0; k < 256; k++)
            acc = fmaf(s[k], W1[k * 256 + tid], acc);
        p[tid] = fmaxf(acc, 0.0f);
    }
    __syncthreads();

    // stage 2: cl = tid&15 (channel in group), q = tid>>4 (k-slice of 16)
    {
        int cl = tid & 15;
        int q = tid >> 4;
        int c = cg * 16 + cl;
        float as = 0.0f, ar = 0.0f, at0 = 0.0f, at1 = 0.0f;
        int k0 = q * 16;
#pragma unroll
        for (int i = 0; i < 16; i++) {
            int row = k0 + i;
            float pv = p[row];
            as  = fmaf(pv, Ws[row * 256 + c], as);
            ar  = fmaf(pv, Wr[row * 256 + c], ar);
            at0 = fmaf(pv, Wt[row * 512 + 2 * c], at0);
            at1 = fmaf(pv, Wt[row * 512 + 2 * c + 1], at1);
        }
        part[tid] = make_float4(as, ar, at0, at1);
    }
    __syncthreads();
    if (tid < 16) {
        int cc = cg * 16 + tid;
        float a0 = bs[cc], a1 = br[cc], a2 = bt[2 * cc], a3 = bt[2 * cc + 1];
#pragma unroll
        for (int qq = 0; qq < 16; qq++) {
            float4 v = part[qq * 16 + tid];
            a0 += v.x; a1 += v.y; a2 += v.z; a3 += v.w;
        }
        float scale = 2.0f / (1.0f + expf(-a0));    // sigmoid * 2
        float angle = tanhf(a1) * PI_F;
        float ca = cosf(angle), sa = sinf(angle);
        float4 o;
        o.x = scale * ca;
        o.y = scale * sa;
        o.z = tanhf(a2);
        o.w = tanhf(a3);
        *(float4*)&g_par[(b * 256 + cc) * 4] = o;
    }
}

// ---------------- Main sampling kernel --------------------------------------
// One block per (b,c). The two z-planes are pre-blended (wz constant per
// block) into ONE SMEM plane stored as DUPLICATED HALF2 PAIRS:
//   P[row][j] = (half(v[row][j]), half(v[row][j+1]))
// so a bilinear tap row needs a single aligned LDS.32 (half the LDS bytes of
// the fp32 layout at the same smem footprint). Zero border (rows/cols
// -1..129) + float-space clamp of coords to [-1,128] reproduces zeros padding.
static constexpr int PSH = 136;                  // half2 pairs per row (544 B)
static constexpr int SROWS = 131;                // rows -1 .. 129
static constexpr int OFF = 4;                    // interior texel 0 -> pair idx 4
static constexpr int PLANE_BYTES = SROWS * PSH * 4;  // 71264

__global__ __launch_bounds__(512, 3)
void sample_kernel(const float* __restrict__ fm, float* __restrict__ out) {
    extern __shared__ __align__(16) char smx[];
    __half2* P = (__half2*)smx;

    int bc = blockIdx.x;
    int b = bc >> 8;
    int c = bc & 255;
    int tid = threadIdx.x;

    const float4 par = *(const float4*)&g_par[bc * 4];
    float m0 = par.x, m1 = par.y, tx = par.z, ty = par.w;

    // z coordinate: iz = 128*zc + 127.5, zc = 2*c/255 - 1
    float zc = fmaf(2.0f / 255.0f, (float)c, -1.0f);
    float iz = fmaf(zc, 128.0f, 127.5f);
    float z0f = floorf(iz);
    float wz = iz - z0f;
    float wza = 1.0f - wz;
    int z0 = (int)z0f;
    int z1 = z0 + 1;
    bool v0 = ((unsigned)z0 < 256u);
    bool v1 = ((unsigned)z1 < 256u);

    const float* base = fm + (size_t)b * (256 * 128 * 128);
    const float4* p0 = (const float4*)(base + (size_t)(v0 ? z0 : 0) * 16384);
    const float4* p1 = (const float4*)(base + (size_t)(v1 ? z1 : 0) * 16384);

    // ---- border zeroing (disjoint from load-phase writes):
    // rows 0,129,130 fully (34 uint4 each = 102), right pair col 132 for rows
    // 1..128 (128 STS.32). 230 threads.
    if (tid < 230) {
        if (tid < 102) {
            int r = tid / 34;                 // 0..2
            int row = (r == 0) ? 0 : (128 + r);
            int col = tid - r * 34;           // 0..33 (uint4 units)
            *(uint4*)((char*)P + (size_t)row * PSH * 4 + col * 16) =
                make_uint4(0, 0, 0, 0);
        } else {
            int r = tid - 101;                // 1..128
            P[r * PSH + OFF + 128] = __float2half2_rn(0.0f);
        }
    }

    // ---- load interior, blend in fp32, pack to half2 pairs.
    // lane == col4 (idx = it*512+tid, 512 % 32 == 0), row = idx>>5.
#pragma unroll
    for (int it = 0; it < 8; it++) {
        int idx = it * 512 + tid;
        int row = idx >> 5;
        int col4 = idx & 31;
        float4 a  = v0 ? p0[idx] : make_float4(0.f, 0.f, 0.f, 0.f);
        float4 bb = v1 ? p1[idx] : make_float4(0.f, 0.f, 0.f, 0.f);
        float r0 = fmaf(wza, a.x, wz * bb.x);
        float r1 = fmaf(wza, a.y, wz * bb.y);
        float r2 = fmaf(wza, a.z, wz * bb.z);
        float r3 = fmaf(wza, a.w, wz * bb.w);
        // next texel (first of the next float4) from lane+1; lane 31 -> border 0
        float r4 = __shfl_down_sync(0xFFFFFFFFu, r0, 1);
        if (col4 == 31) r4 = 0.0f;
        __half h0 = __float2half_rn(r0);
        __half h1 = __float2half_rn(r1);
        __half h2 = __float2half_rn(r2);
        __half h3 = __float2half_rn(r3);
        __half h4 = __float2half_rn(r4);
        __half2 q0 = __halves2half2(h0, h1);
        __half2 q1 = __halves2half2(h1, h2);
        __half2 q2 = __halves2half2(h2, h3);
        __half2 q3 = __halves2half2(h3, h4);
        uint4 pk;
        pk.x = *(unsigned int*)&q0;
        pk.y = *(unsigned int*)&q1;
        pk.z = *(unsigned int*)&q2;
        pk.w = *(unsigned int*)&q3;
        // pair index OFF + col4*4 in row (row+1); byte offset 16B-aligned
        *(uint4*)((char*)P + (size_t)(row + 1) * PSH * 4 + (OFF + col4 * 4) * 4) = pk;
        if (col4 == 0) {
            // left border pair (0, v0)
            P[(row + 1) * PSH + OFF - 1] = __halves2half2(__float2half_rn(0.0f), h0);
        }
    }
    __syncthreads();   // single barrier

    // Affine in index space:
    // ix = 64*gx + 63.5, gx = m0*x - m1*y + tx, x = (2/127)w - 1, y = (2/127)h - 1
    const float s2 = 2.0f / 127.0f;
    float axw = 64.0f * m0 * s2;
    float axh = -64.0f * m1 * s2;
    float cx0 = fmaf(64.0f, tx - m0 + m1, 63.5f);
    float ayw = 64.0f * m1 * s2;
    float ayh = 64.0f * m0 * s2;
    float cy0 = fmaf(64.0f, ty - m1 - m0, 63.5f);

    int w  = tid & 127;          // constant per thread across the loop
    int h0i = tid >> 7;          // 0..3; h steps by 4 each iteration
    float ix = axw * (float)w + axh * (float)h0i + cx0;
    float iy = ayw * (float)w + ayh * (float)h0i + cy0;
    float dix = 4.0f * axh;
    float diy = 4.0f * ayh;

    const __half2* SP = P + PSH + OFF;      // pair for interior (cy,cx)=(0,0)
    float* op = out + (size_t)bc * 16384 + tid;

#pragma unroll 8
    for (int k = 0; k < 32; k++) {
        // Clamp in FLOAT space BEFORE floor: out-of-range taps land entirely
        // on zero border cells with correct weights (matches zeros padding).
        float ixc = fminf(fmaxf(ix, -1.0f), 128.0f);
        float iyc = fminf(fmaxf(iy, -1.0f), 128.0f);
        int cx = __float2int_rd(ixc);       // in [-1,128]
        int cy = __float2int_rd(iyc);
        float fx = ixc - (float)cx;
        float fy = iyc - (float)cy;
        const __half2* pp = SP + cy * PSH + cx;
        float2 t = __half22float2(pp[0]);       // (v00, v01)
        float2 bo = __half22float2(pp[PSH]);    // (v10, v11)
        float top = fmaf(fx, t.y - t.x, t.x);
        float bot = fmaf(fx, bo.y - bo.x, bo.x);
        op[(size_t)k * 512] = fmaf(fy, bot - top, top);
        ix += dix;
        iy += diy;
    }
}

// ---------------- launch --------------------------------------------------
extern "C" void kernel_launch(void* const* d_in, const int* in_sizes, int n_in,
                              void* d_out, int out_size) {
    const float* feature_map = (const float*)d_in[0];  // [4,256,128,128]
    const float* para_code   = (const float*)d_in[1];  // [4,256]
    const float* W1 = (const float*)d_in[2];
    const float* b1 = (const float*)d_in[3];
    const float* Ws = (const float*)d_in[4];
    const float* bs = (const float*)d_in[5];
    const float* Wr = (const float*)d_in[6];
    const float* br = (const float*)d_in[7];
    const float* Wt = (const float*)d_in[8];
    const float* bt = (const float*)d_in[9];
    float* out = (float*)d_out;

    cudaFuncSetAttribute(sample_kernel, cudaFuncAttributeMaxDynamicSharedMemorySize,
                         PLANE_BYTES);

    mlp_fused_kernel<<<64, 256>>>(para_code, W1, b1, Ws, bs, Wr, br, Wt, bt);
    sample_kernel<<<1024, 512, PLANE_BYTES>>>(feature_map, out);
}

// round 13
// speedup vs baseline: 1.3896x; 1.3896x over previous
#include <cuda_runtime.h>
#include <cuda_fp16.h>
#include <math.h>

#define PI_F 3.14159f

// Scratch: __device__ globals (no allocation allowed)
__device__ float g_p[4 * 256];          // relu(pc @ W1 + b1)
__device__ float g_WsT[256 * 256];      // Ws transposed: [c][k]
__device__ float g_WrT[256 * 256];      // Wr transposed: [c][k]
__device__ float g_WtT[512 * 256];      // Wt transposed: [col][k]

// ---------------- prep kernel: mlp1 (blocks 0..63) + transposes -------------
__device__ __forceinline__ void transpose_tile(const float* __restrict__ M,
                                               float* __restrict__ MT,
                                               int R, int C, int idx, int tid) {
    __shared__ float t[32][33];
    int tpr = C >> 5;                 // tiles per row of M
    int ti = idx / tpr;               // row-tile
    int tj = idx - ti * tpr;          // col-tile
    int tx = tid & 31;
    int ty = tid >> 5;                // 0..7
#pragma unroll
    for (int yy = 0; yy < 32; yy += 8)
        t[yy + ty][tx] = M[(ti * 32 + yy + ty) * C + tj * 32 + tx];
    __syncthreads();
#pragma unroll
    for (int yy = 0; yy < 32; yy += 8)
        MT[(tj * 32 + yy + ty) * R + ti * 32 + tx] = t[tx][yy + ty];
}

__global__ void prep_kernel(const float* __restrict__ pc,
                            const float* __restrict__ W1, const float* __restrict__ b1,
                            const float* __restrict__ Ws,
                            const float* __restrict__ Wr,
                            const float* __restrict__ Wt) {
    int blk = blockIdx.x;
    int tid = threadIdx.x;
    if (blk < 64) {
        // wide mlp1: b = blk>>4, jg = blk&15; jl = tid&15, q = tid>>4
        int b = blk >> 4;
        int jg = blk & 15;
        int jl = tid & 15;
        int q = tid >> 4;
        int j = jg * 16 + jl;
        __shared__ float s[256];
        __shared__ float part[256];
        s[tid] = pc[b * 256 + tid];
        __syncthreads();
        float acc = 0.0f;
        int k0 = q * 16;
#pragma unroll
        for (int i = 0; i < 16; i++)
            acc = fmaf(s[k0 + i], W1[(k0 + i) * 256 + j], acc);
        part[tid] = acc;
        __syncthreads();
        if (tid < 16) {
            float a = b1[jg * 16 + tid];
#pragma unroll
            for (int qq = 0; qq < 16; qq++) a += part[qq * 16 + tid];
            g_p[b * 256 + jg * 16 + tid] = fmaxf(a, 0.0f);
        }
    } else if (blk < 128) {
        transpose_tile(Ws, g_WsT, 256, 256, blk - 64, tid);
    } else if (blk < 192) {
        transpose_tile(Wr, g_WrT, 256, 256, blk - 128, tid);
    } else {
        transpose_tile(Wt, g_WtT, 256, 512, blk - 192, tid);
    }
}

// ---------------- Main sampling kernel (coalesced mlp2 fused) ---------------
// One block per (b,c). Two z-planes pre-blended (wz constant per block) into
// ONE SMEM plane of DUPLICATED HALF2 PAIRS: P[row][j]=(h(v[j]),h(v[j+1])),
// so each bilinear tap row is a single aligned LDS.32. Zero border rows/cols
// -1..129 + float-space clamp of coords to [-1,128] == zeros padding.
// The per-(b,c) head GEMVs read TRANSPOSED weights (coalesced, L2-hot) and
// are hidden behind the plane LDGs.
static constexpr int PSH = 136;                  // half2 pairs per row (544 B)
static constexpr int SROWS = 131;                // rows -1 .. 129
static constexpr int OFF = 4;                    // interior texel 0 -> pair idx 4
static constexpr int PLANE_BYTES = SROWS * PSH * 4;      // 71264
static constexpr int SMEM_TOTAL = PLANE_BYTES + 128;     // + reduce scratch

__global__ __launch_bounds__(512, 3)
void sample_kernel(const float* __restrict__ fm, float* __restrict__ out,
                   const float* __restrict__ bs, const float* __restrict__ br,
                   const float* __restrict__ bt) {
    extern __shared__ __align__(16) char smx[];
    __half2* P = (__half2*)smx;
    float* red = (float*)(smx + PLANE_BYTES);   // [16] warp partials
    float* prm = red + 16;                      // [4] m0,m1,tx,ty

    int bc = blockIdx.x;
    int b = bc >> 8;
    int c = bc & 255;
    int tid = threadIdx.x;

    // z coordinate: iz = 128*zc + 127.5, zc = 2*c/255 - 1
    float zc = fmaf(2.0f / 255.0f, (float)c, -1.0f);
    float iz = fmaf(zc, 128.0f, 127.5f);
    float z0f = floorf(iz);
    float wz = iz - z0f;
    float wza = 1.0f - wz;
    int z0 = (int)z0f;
    int z1 = z0 + 1;
    bool v0 = ((unsigned)z0 < 256u);
    bool v1 = ((unsigned)z1 < 256u);

    const float* base = fm + (size_t)b * (256 * 128 * 128);
    const float4* p0 = (const float4*)(base + (size_t)(v0 ? z0 : 0) * 16384);
    const float4* p1 = (const float4*)(base + (size_t)(v1 ? z1 : 0) * 16384);

    // ---- border zeroing (disjoint from load-phase writes):
    // rows 0,129,130 fully (34 uint4 each = 102), right pair col for rows
    // 1..128 (128 STS.32). 230 threads.
    if (tid < 230) {
        if (tid < 102) {
            int r = tid / 34;                 // 0..2
            int row = (r == 0) ? 0 : (128 + r);
            int col = tid - r * 34;           // 0..33 (uint4 units)
            *(uint4*)((char*)P + (size_t)row * PSH * 4 + col * 16) =
                make_uint4(0, 0, 0, 0);
        } else {
            int r = tid - 101;                // 1..128
            P[r * PSH + OFF + 128] = __float2half2_rn(0.0f);
        }
    }

    // ---- load interior, blend in fp32, pack to half2 pairs.
#pragma unroll
    for (int it = 0; it < 8; it++) {
        int idx = it * 512 + tid;
        int row = idx >> 5;
        int col4 = idx & 31;
        float4 a  = v0 ? p0[idx] : make_float4(0.f, 0.f, 0.f, 0.f);
        float4 bb = v1 ? p1[idx] : make_float4(0.f, 0.f, 0.f, 0.f);
        float r0 = fmaf(wza, a.x, wz * bb.x);
        float r1 = fmaf(wza, a.y, wz * bb.y);
        float r2 = fmaf(wza, a.z, wz * bb.z);
        float r3 = fmaf(wza, a.w, wz * bb.w);
        float r4 = __shfl_down_sync(0xFFFFFFFFu, r0, 1);
        if (col4 == 31) r4 = 0.0f;
        __half h0 = __float2half_rn(r0);
        __half h1 = __float2half_rn(r1);
        __half h2 = __float2half_rn(r2);
        __half h3 = __float2half_rn(r3);
        __half h4 = __float2half_rn(r4);
        __half2 q0 = __halves2half2(h0, h1);
        __half2 q1 = __halves2half2(h1, h2);
        __half2 q2 = __halves2half2(h2, h3);
        __half2 q3 = __halves2half2(h3, h4);
        uint4 pk;
        pk.x = *(unsigned int*)&q0;
        pk.y = *(unsigned int*)&q1;
        pk.z = *(unsigned int*)&q2;
        pk.w = *(unsigned int*)&q3;
        *(uint4*)((char*)P + (size_t)(row + 1) * PSH * 4 + (OFF + col4 * 4) * 4) = pk;
        if (col4 == 0)
            P[(row + 1) * PSH + OFF - 1] = __halves2half2(__float2half_rn(0.0f), h0);
    }

    // ---- fused mlp2 with TRANSPOSED (coalesced) weights, overlapping the
    // plane LDGs above. 4 heads x 128 threads, 2 k-rows each.
    {
        int r = tid & 127;
        int h = tid >> 7;                 // 0..3
        const float* pv = g_p + b * 256;
        const float* Wv;
        if (h == 0)      Wv = g_WsT + (size_t)c * 256;
        else if (h == 1) Wv = g_WrT + (size_t)c * 256;
        else if (h == 2) Wv = g_WtT + (size_t)(2 * c) * 256;
        else             Wv = g_WtT + (size_t)(2 * c + 1) * 256;
        float acc = pv[r] * Wv[r] + pv[r + 128] * Wv[r + 128];
#pragma unroll
        for (int off = 16; off; off >>= 1)
            acc += __shfl_down_sync(0xFFFFFFFFu, acc, off);
        if ((tid & 31) == 0) red[tid >> 5] = acc;   // warp 0..15
    }
    __syncthreads();   // plane + border + partials ready

    if (tid < 4) {
        float a = red[tid * 4] + red[tid * 4 + 1] + red[tid * 4 + 2] + red[tid * 4 + 3];
        float bias = (tid == 0) ? bs[c] : (tid == 1) ? br[c]
                   : (tid == 2) ? bt[2 * c] : bt[2 * c + 1];
        float v = a + bias;
        // tid 0..3 are in warp 0: gather all four raw values into lane 0
        float v0r = __shfl_sync(0x0000000Fu, v, 0, 4);
        float v1r = __shfl_sync(0x0000000Fu, v, 1, 4);
        float v2r = __shfl_sync(0x0000000Fu, v, 2, 4);
        float v3r = __shfl_sync(0x0000000Fu, v, 3, 4);
        if (tid == 0) {
            float scale = 2.0f / (1.0f + expf(-v0r));
            float angle = tanhf(v1r) * PI_F;
            prm[0] = scale * cosf(angle);
            prm[1] = scale * sinf(angle);
            prm[2] = tanhf(v2r);
            prm[3] = tanhf(v3r);
        }
    }
    __syncthreads();

    float m0 = prm[0], m1 = prm[1], tx = prm[2], ty = prm[3];

    // Affine in index space:
    // ix = 64*gx + 63.5, gx = m0*x - m1*y + tx, x = (2/127)w - 1, y = (2/127)h - 1
    const float s2 = 2.0f / 127.0f;
    float axw = 64.0f * m0 * s2;
    float axh = -64.0f * m1 * s2;
    float cx0 = fmaf(64.0f, tx - m0 + m1, 63.5f);
    float ayw = 64.0f * m1 * s2;
    float ayh = 64.0f * m0 * s2;
    float cy0 = fmaf(64.0f, ty - m1 - m0, 63.5f);

    int w  = tid & 127;          // constant per thread across the loop
    int h0i = tid >> 7;          // 0..3; h steps by 4 each iteration
    float ix = axw * (float)w + axh * (float)h0i + cx0;
    float iy = ayw * (float)w + ayh * (float)h0i + cy0;
    float dix = 4.0f * axh;
    float diy = 4.0f * ayh;

    const __half2* SP = P + PSH + OFF;      // pair for interior (cy,cx)=(0,0)
    float* op = out + (size_t)bc * 16384 + tid;

#pragma unroll 8
    for (int k = 0; k < 32; k++) {
        // Clamp in FLOAT space BEFORE floor: out-of-range taps land entirely
        // on zero border cells with correct weights (matches zeros padding).
        float ixc = fminf(fmaxf(ix, -1.0f), 128.0f);
        float iyc = fminf(fmaxf(iy, -1.0f), 128.0f);
        int cx = __float2int_rd(ixc);       // in [-1,128]
        int cy = __float2int_rd(iyc);
        float fx = ixc - (float)cx;
        float fy = iyc - (float)cy;
        const __half2* pp = SP + cy * PSH + cx;
        float2 t = __half22float2(pp[0]);       // (v00, v01)
        float2 bo = __half22float2(pp[PSH]);    // (v10, v11)
        float top = fmaf(fx, t.y - t.x, t.x);
        float bot = fmaf(fx, bo.y - bo.x, bo.x);
        op[(size_t)k * 512] = fmaf(fy, bot - top, top);
        ix += dix;
        iy += diy;
    }
}

// ---------------- launch --------------------------------------------------
extern "C" void kernel_launch(void* const* d_in, const int* in_sizes, int n_in,
                              void* d_out, int out_size) {
    const float* feature_map = (const float*)d_in[0];  // [4,256,128,128]
    const float* para_code   = (const float*)d_in[1];  // [4,256]
    const float* W1 = (const float*)d_in[2];
    const float* b1 = (const float*)d_in[3];
    const float* Ws = (const float*)d_in[4];
    const float* bs = (const float*)d_in[5];
    const float* Wr = (const float*)d_in[6];
    const float* br = (const float*)d_in[7];
    const float* Wt = (const float*)d_in[8];
    const float* bt = (const float*)d_in[9];
    float* out = (float*)d_out;

    cudaFuncSetAttribute(sample_kernel, cudaFuncAttributeMaxDynamicSharedMemorySize,
                         SMEM_TOTAL);

    prep_kernel<<<320, 256>>>(para_code, W1, b1, Ws, Wr, Wt);
    sample_kernel<<<1024, 512, SMEM_TOTAL>>>(feature_map, out, bs, br, bt);
}